// round 11
// baseline (speedup 1.0000x reference)
#include <cuda_runtime.h>

#define BB 512
#define TT 1024
#define HH 100
#define VV 62

typedef unsigned long long ull;

// ping-pong time-major [T][B][H] activation buffers (no cudaMalloc allowed)
__device__ float g_bufA[(size_t)TT * BB * HH];
__device__ float g_bufB[(size_t)TT * BB * HH];

// packed dual-fp32 FMA: d.lo += a.lo*b.lo ; d.hi += a.hi*b.hi
__device__ __forceinline__ void fma2(ull& d, ull a, ull b) {
    asm("fma.rn.f32x2 %0, %1, %2, %0;" : "+l"(d) : "l"(a), "l"(b));
}
__device__ __forceinline__ float red2(ull v) {
    return __uint_as_float((unsigned)v) + __uint_as_float((unsigned)(v >> 32));
}
// fast tanh: 1 - 2/(e^{2x}+1); __expf saturates to inf -> result -> 1. OK.
__device__ __forceinline__ float ftanh(float x) {
    float e = __expf(x + x);
    return 1.0f - __fdividef(2.0f, e + 1.0f);
}

// ---------------------------------------------------------------------------
// 1) embedding gather (3 launches so ncu -s5 lands on proj#2):
// ---------------------------------------------------------------------------
__global__ void k_gather(const int* __restrict__ ids,
                         const float* __restrict__ emb,
                         float* __restrict__ out, int base, int count) {
    int idx = base + blockIdx.x * blockDim.x + threadIdx.x;
    if (idx >= base + count || idx >= TT * BB * 25) return;
    int c  = idx % 25;
    int tb = idx / 25;
    int b  = tb % BB;
    int t  = tb / BB;
    int id = ids[(size_t)b * TT + t];
    float4 v = ((const float4*)(emb + (size_t)id * HH))[c];
    ((float4*)(out + ((size_t)t * BB + b) * HH))[c] = v;
}

// ---------------------------------------------------------------------------
// 2) input projection: Y[row][k] = sum_j X[row][j]*W[k][j] + bi[k] + bh[k]
// 256 thr = 8 warps; warp w owns 13 k-rows (k0=13w), lanes own 2 rows
// (lane, lane+32) of a 64-row tile. Per j4: 13 broadcast W loads + 8 X
// wavefronts = 21 wf vs 104 fma-cyc -> fma-bound (2.48:1). OCC 2.
// ---------------------------------------------------------------------------
#define PROJ_T 256
#define PROJ_ROWS 64
__global__ void __launch_bounds__(PROJ_T, 2) k_proj(const float* __restrict__ X,
                                                    const float* __restrict__ W,
                                                    const float* __restrict__ bi,
                                                    const float* __restrict__ bh,
                                                    float* __restrict__ Y) {
    extern __shared__ float sm[];
    float* Ws = sm;             // [104][100] zero-padded rows 100..103
    float* Xs = sm + 10400;     // [64][100]
    float* bs = sm + 16800;     // [104]

    int tid = threadIdx.x;
    float4* Ws4 = (float4*)Ws;
    const float4* Wg = (const float4*)W;
    for (int i = tid; i < 2600; i += PROJ_T) {      // 104*25
        int k = i / 25;
        float4 z = {0.f, 0.f, 0.f, 0.f};
        Ws4[i] = (k < HH) ? Wg[i] : z;
    }
    if (tid < 104) bs[tid] = (tid < HH) ? (bi[tid] + bh[tid]) : 0.f;

    size_t row0 = (size_t)blockIdx.x * PROJ_ROWS;
    float4* Xs4 = (float4*)Xs;
    const float4* Xg = (const float4*)X;
    for (int i = tid; i < PROJ_ROWS * 25; i += PROJ_T) Xs4[i] = Xg[row0 * 25 + i];
    __syncthreads();

    int w    = tid >> 5;        // warp 0..7
    int lane = tid & 31;
    int k0   = w * 13;          // 13 k-rows per warp, 8*13 = 104

    const ulonglong2* Wu = (const ulonglong2*)Ws;
    const ulonglong2* Xu = (const ulonglong2*)Xs;

    ull acc[13][2];
#pragma unroll
    for (int c = 0; c < 13; c++) { acc[c][0] = 0ull; acc[c][1] = 0ull; }

#pragma unroll 5
    for (int j4 = 0; j4 < 25; j4++) {
        ulonglong2 x0 = Xu[(lane +  0) * 25 + j4];
        ulonglong2 x1 = Xu[(lane + 32) * 25 + j4];
#pragma unroll
        for (int c = 0; c < 13; c++) {
            ulonglong2 wv = Wu[(k0 + c) * 25 + j4];   // warp-broadcast
            fma2(acc[c][0], wv.x, x0.x); fma2(acc[c][0], wv.y, x0.y);
            fma2(acc[c][1], wv.x, x1.x); fma2(acc[c][1], wv.y, x1.y);
        }
    }

#pragma unroll
    for (int c = 0; c < 13; c++) {
        int k = k0 + c;
        if (k < HH) {
            float bk = bs[k];
            Y[(row0 + lane) * HH + k]      = red2(acc[c][0]) + bk;
            Y[(row0 + lane + 32) * HH + k] = red2(acc[c][1]) + bk;
        }
    }
}

// ---------------------------------------------------------------------------
// 3) recurrent scan (R6 design + NAMED barriers): h_new = tanh(xin + h@Wh^T)
// 128 blocks (1/SM) x 256 threads = two INDEPENDENT 128-thread groups
// (2 batch rows each), each synced by its own bar.sync id -> no cross-group
// straggling. Thread k holds W[k][:] in 100 regs; h via smem broadcast.
// ---------------------------------------------------------------------------
__global__ void __launch_bounds__(256, 1) k_rnn(float* __restrict__ XY,
                                                const float* __restrict__ W,
                                                float* __restrict__ hout) {
    __shared__ __align__(16) float hs[2][4][104];

    int tid = threadIdx.x;
    int g   = tid >> 7;          // row-group 0/1
    int k   = tid & 127;
    int kk  = (k < HH) ? k : (HH - 1);
    int r0  = g * 2;
    int barid = 1 + g;

    ulonglong2 wv[25];           // W[kk][0..99]
    const ulonglong2* Wg = (const ulonglong2*)W;
#pragma unroll
    for (int i = 0; i < 25; i++) wv[i] = Wg[kk * 25 + i];

    if (tid < 104) {
        hs[0][0][tid] = 0.f; hs[0][1][tid] = 0.f;
        hs[0][2][tid] = 0.f; hs[0][3][tid] = 0.f;
    }
    __syncthreads();

    int b0 = blockIdx.x * 4 + r0;            // this group's first batch row
    const size_t st = (size_t)BB * HH;
    const float* px = XY + (size_t)b0 * HH + kk;

    float c0 = px[0], c1 = px[HH];
    int p = 0;

    for (int t = 0; t < TT; t++) {
        size_t tn = (size_t)((t + 1 < TT) ? t + 1 : t) * st;
        float n0 = px[tn], n1 = px[tn + HH];  // prefetch next xin

        ull a0l = 0, a0h = 0, a1l = 0, a1h = 0;
        const ulonglong2* h0p = (const ulonglong2*)&hs[p][r0][0];
        const ulonglong2* h1p = (const ulonglong2*)&hs[p][r0 + 1][0];
#pragma unroll
        for (int j = 0; j < 25; j++) {
            ulonglong2 w  = wv[j];
            ulonglong2 h0 = h0p[j];           // broadcast loads
            ulonglong2 h1 = h1p[j];
            fma2(a0l, w.x, h0.x); fma2(a0h, w.y, h0.y);
            fma2(a1l, w.x, h1.x); fma2(a1h, w.y, h1.y);
        }
        float z0 = ftanh(red2(a0l) + red2(a0h) + c0);
        float z1 = ftanh(red2(a1l) + red2(a1h) + c1);

        if (k < HH) {
            hs[p ^ 1][r0][k]     = z0;
            hs[p ^ 1][r0 + 1][k] = z1;
            float* py = XY + (size_t)t * st + (size_t)b0 * HH + k;
            py[0] = z0; py[HH] = z1;
        }
        asm volatile("bar.sync %0, %1;" :: "r"(barid), "r"(128) : "memory");
        p ^= 1;
        c0 = n0; c1 = n1;
    }

    if (k < HH) {
        hout[(size_t)b0 * HH + k]       = hs[p][r0][k];
        hout[(size_t)(b0 + 1) * HH + k] = hs[p][r0 + 1][k];
    }
}

// ---------------------------------------------------------------------------
// 4) decoder: logits[b][t][v] = dot(ys[t][b][:], Wd[v][:]) + bd[v]
// 128 thr = 4 warps; warp w owns 16 v-rows (V padded 64), lanes own 2 rows
// of a 64-row tile. Per j4: 16 W + 8 X wf = 24 vs 128 fma-cyc (2.67:1).
// ---------------------------------------------------------------------------
#define DEC_T 128
__global__ void __launch_bounds__(DEC_T, 4) k_dec(const float* __restrict__ Ys,
                                                  const float* __restrict__ Wd,
                                                  const float* __restrict__ bd,
                                                  float* __restrict__ out) {
    extern __shared__ float sm[];
    float* Ws = sm;            // [64][100] zero-padded
    float* Xs = sm + 6400;     // [64][100]
    float* bs = sm + 12800;    // [64]

    int tid = threadIdx.x;
    for (int i = tid; i < 6400; i += DEC_T) Ws[i] = (i < VV * HH) ? Wd[i] : 0.f;
    if (tid < 64) bs[tid] = (tid < VV) ? bd[tid] : 0.f;

    size_t row0 = (size_t)blockIdx.x * 64;
    float4* Xs4 = (float4*)Xs;
    const float4* Yg = (const float4*)Ys;
    for (int i = tid; i < 1600; i += DEC_T) Xs4[i] = Yg[row0 * 25 + i];
    __syncthreads();

    int w    = tid >> 5;       // 0..3
    int lane = tid & 31;
    int v0   = w * 16;

    const ulonglong2* Wu = (const ulonglong2*)Ws;
    const ulonglong2* Xu = (const ulonglong2*)Xs;

    ull acc[16][2];
#pragma unroll
    for (int c = 0; c < 16; c++) { acc[c][0] = 0ull; acc[c][1] = 0ull; }

#pragma unroll 5
    for (int j4 = 0; j4 < 25; j4++) {
        ulonglong2 x0 = Xu[(lane +  0) * 25 + j4];
        ulonglong2 x1 = Xu[(lane + 32) * 25 + j4];
#pragma unroll
        for (int c = 0; c < 16; c++) {
            ulonglong2 wv = Wu[(v0 + c) * 25 + j4];   // warp-broadcast
            fma2(acc[c][0], wv.x, x0.x); fma2(acc[c][0], wv.y, x0.y);
            fma2(acc[c][1], wv.x, x1.x); fma2(acc[c][1], wv.y, x1.y);
        }
    }

    size_t rowA = row0 + lane;          // = t*BB + b
    size_t rowB = row0 + lane + 32;
    float* oA = out + ((rowA & 511) * TT + (rowA >> 9)) * VV;
    float* oB = out + ((rowB & 511) * TT + (rowB >> 9)) * VV;
#pragma unroll
    for (int c = 0; c < 16; c++) {
        int v = v0 + c;
        if (v < VV) {
            float bv = bs[v];
            oA[v] = red2(acc[c][0]) + bv;
            oB[v] = red2(acc[c][1]) + bv;
        }
    }
}

// ---------------------------------------------------------------------------
extern "C" void kernel_launch(void* const* d_in, const int* in_sizes, int n_in,
                              void* d_out, int out_size) {
    const int*   ids   = (const int*)d_in[0];
    const float* emb   = (const float*)d_in[1];
    const float* W_ih  = (const float*)d_in[2];   // [3][100][100]
    const float* W_hh  = (const float*)d_in[3];   // [3][100][100]
    const float* b_ih  = (const float*)d_in[4];   // [3][100]
    const float* b_hh  = (const float*)d_in[5];   // [3][100]
    const float* W_dec = (const float*)d_in[6];   // [62][100]
    const float* b_dec = (const float*)d_in[7];   // [62]
    float* out = (float*)d_out;

    float *bufA, *bufB;
    cudaGetSymbolAddress((void**)&bufA, g_bufA);
    cudaGetSymbolAddress((void**)&bufB, g_bufB);

    const int proj_smem = 16904 * (int)sizeof(float);   // ~67.6 KB
    const int dec_smem  = 12864 * (int)sizeof(float);   // ~51.5 KB
    cudaFuncSetAttribute(k_proj, cudaFuncAttributeMaxDynamicSharedMemorySize, proj_smem);
    cudaFuncSetAttribute(k_dec,  cudaFuncAttributeMaxDynamicSharedMemorySize, dec_smem);

    float* hid = out + (size_t)BB * TT * VV;
    const int NPROJ = (TT * BB) / PROJ_ROWS;   // 8192
    const int NDEC  = (TT * BB) / 64;          // 8192

    // gather in 3 launches (ncu -s5 alignment: idx5 = proj#2)
    {
        int total = TT * BB * 25;
        int third = total / 3;
        k_gather<<<(third + 255) / 256, 256>>>(ids, emb, bufA, 0, third);
        k_gather<<<(third + 255) / 256, 256>>>(ids, emb, bufA, third, third);
        int rest = total - 2 * third;
        k_gather<<<(rest + 255) / 256, 256>>>(ids, emb, bufA, 2 * third, rest);
    }

    // layer 0
    k_proj<<<NPROJ, PROJ_T, proj_smem>>>(bufA, W_ih, b_ih, b_hh, bufB);
    k_rnn<<<BB / 4, 256>>>(bufB, W_hh, hid);
    // layer 1
    k_proj<<<NPROJ, PROJ_T, proj_smem>>>(bufB, W_ih + 10000, b_ih + 100, b_hh + 100, bufA);
    k_rnn<<<BB / 4, 256>>>(bufA, W_hh + 10000, hid + (size_t)BB * HH);
    // layer 2
    k_proj<<<NPROJ, PROJ_T, proj_smem>>>(bufA, W_ih + 20000, b_ih + 200, b_hh + 200, bufB);
    k_rnn<<<BB / 4, 256>>>(bufB, W_hh + 20000, hid + 2 * (size_t)BB * HH);

    k_dec<<<NDEC, DEC_T, dec_smem>>>(bufB, W_dec, b_dec, out);
}

// round 16
// speedup vs baseline: 1.3139x; 1.3139x over previous
#include <cuda_runtime.h>
#include <cuda_bf16.h>
#include <cstdint>

#define BB 512
#define TT 1024
#define HH 100
#define VV 62

typedef unsigned long long ull;

// ping-pong time-major [T][B][H] activation buffers (no cudaMalloc allowed)
__device__ float g_bufA[(size_t)TT * BB * HH];
__device__ float g_bufB[(size_t)TT * BB * HH];
// prepped bf16 weights: rows 0..311 = W_ih (3 layers x 104 padded rows),
// rows 312..375 = W_dec (64 padded rows); 112 cols (K padded), hi + lo split
__device__ __nv_bfloat16 g_Whi[376 * 112];
__device__ __nv_bfloat16 g_Wlo[376 * 112];

// ---------------- SIMT helpers (rnn) ----------------
__device__ __forceinline__ void fma2(ull& d, ull a, ull b) {
    asm("fma.rn.f32x2 %0, %1, %2, %0;" : "+l"(d) : "l"(a), "l"(b));
}
__device__ __forceinline__ float red2(ull v) {
    return __uint_as_float((unsigned)v) + __uint_as_float((unsigned)(v >> 32));
}
__device__ __forceinline__ float ftanh(float x) {
    float e = __expf(x + x);
    return 1.0f - __fdividef(2.0f, e + 1.0f);
}

// ---------------- HMMA helper ----------------
// D(m16n8, f32) += A(m16k16, bf16 row-major) * B(k16n8, bf16 col-major)
__device__ __forceinline__ void mma16816(float* d, const uint32_t* a, const uint32_t* b) {
    asm volatile(
        "mma.sync.aligned.m16n8k16.row.col.f32.bf16.bf16.f32 "
        "{%0,%1,%2,%3}, {%4,%5,%6,%7}, {%8,%9}, {%0,%1,%2,%3};"
        : "+f"(d[0]), "+f"(d[1]), "+f"(d[2]), "+f"(d[3])
        : "r"(a[0]), "r"(a[1]), "r"(a[2]), "r"(a[3]), "r"(b[0]), "r"(b[1]));
}

__device__ __forceinline__ uint32_t pack_bf2(__nv_bfloat16 a, __nv_bfloat16 b) {
    __nv_bfloat162 t = __halves2bfloat162(a, b);
    return *reinterpret_cast<uint32_t*>(&t);
}
// 8 floats -> 4 bf16x2 hi + 4 bf16x2 lo(residual)
__device__ __forceinline__ void cvt8(const float* v, uint32_t* hi, uint32_t* lo) {
#pragma unroll
    for (int i = 0; i < 4; i++) {
        float a = v[2 * i], b = v[2 * i + 1];
        __nv_bfloat16 ha = __float2bfloat16_rn(a), hb = __float2bfloat16_rn(b);
        __nv_bfloat16 la = __float2bfloat16_rn(a - __bfloat162float(ha));
        __nv_bfloat16 lb = __float2bfloat16_rn(b - __bfloat162float(hb));
        hi[i] = pack_bf2(ha, hb);
        lo[i] = pack_bf2(la, lb);
    }
}

// ---------------------------------------------------------------------------
// weight prep: fp32 W rows -> bf16 hi/lo, K padded 100->112, N rows padded.
// row idx: [0,312) = W_ih (l = idx/104, n = idx%104) ; [312,376) = W_dec.
// ---------------------------------------------------------------------------
__global__ void k_wprep(const float* __restrict__ W_ih,
                        const float* __restrict__ W_dec,
                        __nv_bfloat16* __restrict__ hi,
                        __nv_bfloat16* __restrict__ lo) {
    int idx = blockIdx.x * blockDim.x + threadIdx.x;
    if (idx >= 376) return;
    const float* src = nullptr;
    if (idx < 312) {
        int l = idx / 104, n = idx % 104;
        if (n < HH) src = W_ih + (size_t)l * 10000 + n * HH;
    } else {
        int n = idx - 312;
        if (n < VV) src = W_dec + (size_t)n * HH;
    }
    __nv_bfloat16* dh = hi + (size_t)idx * 112;
    __nv_bfloat16* dl = lo + (size_t)idx * 112;
    for (int c = 0; c < 112; c++) {
        float v = (src && c < HH) ? src[c] : 0.f;
        __nv_bfloat16 h = __float2bfloat16_rn(v);
        __nv_bfloat16 r = __float2bfloat16_rn(v - __bfloat162float(h));
        dh[c] = h; dl[c] = r;
    }
}

// ---------------------------------------------------------------------------
// tensor GEMM tile: D[128, NVAL] = X[128,100] @ W[NVAL,100]^T + bias
// bf16 2-split via 3 HMMA passes. Block 128 thr (4 warps); warp w owns
// m-tiles {2w,2w+1}; NTN n-tiles of 8. K = 7 chunks of 16 (pad 112).
// smem stride 120 bf16 -> conflict-free fragment loads.
// DEC=false: Y[row][k] row-major. DEC=true: out[(b*TT+t)*VV+v], row=t*BB+b.
// ---------------------------------------------------------------------------
template <int NPAD, int NTN, int NVAL, bool DEC>
__global__ void __launch_bounds__(128, 1)
k_gemm(const float* __restrict__ X,
       const __nv_bfloat16* __restrict__ Wh_g,
       const __nv_bfloat16* __restrict__ Wl_g,
       const float* __restrict__ b1, const float* __restrict__ b2,
       float* __restrict__ Y) {
    extern __shared__ char smraw[];
    __nv_bfloat16* Xhi = (__nv_bfloat16*)smraw;          // [128][120]
    __nv_bfloat16* Xlo = Xhi + 128 * 120;                // [128][120]
    __nv_bfloat16* Whi = Xlo + 128 * 120;                // [NPAD][120]
    __nv_bfloat16* Wlo = Whi + NPAD * 120;               // [NPAD][120]
    float* bs = (float*)(Wlo + NPAD * 120);              // [NPAD]

    int tid = threadIdx.x;
    size_t row0 = (size_t)blockIdx.x * 128;

    // ---- stage X row `tid` (fp32 -> bf16 hi/lo, K pad zeroed) ----
    {
        const float4* src = (const float4*)(X + (row0 + tid) * HH);
        char* hb = (char*)Xhi + tid * 240;
        char* lb = (char*)Xlo + tid * 240;
#pragma unroll
        for (int gg = 0; gg < 12; gg++) {
            float4 va = src[2 * gg], vb = src[2 * gg + 1];
            float v[8] = {va.x, va.y, va.z, va.w, vb.x, vb.y, vb.z, vb.w};
            uint32_t h4[4], l4[4];
            cvt8(v, h4, l4);
            *(uint4*)(hb + 16 * gg) = make_uint4(h4[0], h4[1], h4[2], h4[3]);
            *(uint4*)(lb + 16 * gg) = make_uint4(l4[0], l4[1], l4[2], l4[3]);
        }
        float4 vc = src[24];
        float v[8] = {vc.x, vc.y, vc.z, vc.w, 0.f, 0.f, 0.f, 0.f};
        uint32_t h4[4], l4[4];
        cvt8(v, h4, l4);
        *(uint4*)(hb + 192) = make_uint4(h4[0], h4[1], h4[2], h4[3]);
        *(uint4*)(lb + 192) = make_uint4(l4[0], l4[1], l4[2], l4[3]);
        *(uint4*)(hb + 208) = make_uint4(0, 0, 0, 0);
        *(uint4*)(lb + 208) = make_uint4(0, 0, 0, 0);
    }
    // ---- stage W rows (prepped bf16 global -> smem stride 120) ----
    if (tid < NPAD) {
        const uint4* sh = (const uint4*)(Wh_g + (size_t)tid * 112);
        const uint4* sl = (const uint4*)(Wl_g + (size_t)tid * 112);
        char* dh = (char*)Whi + tid * 240;
        char* dl = (char*)Wlo + tid * 240;
#pragma unroll
        for (int gg = 0; gg < 14; gg++) {
            *(uint4*)(dh + 16 * gg) = sh[gg];
            *(uint4*)(dl + 16 * gg) = sl[gg];
        }
        float bv = 0.f;
        if (tid < NVAL) bv = b2 ? (b1[tid] + b2[tid]) : b1[tid];
        bs[tid] = bv;
    }
    __syncthreads();

    int w = tid >> 5, lane = tid & 31;
    int g = lane >> 2, t = lane & 3;

    const uint32_t* Xh = (const uint32_t*)Xhi;   // word views (stride 60 words)
    const uint32_t* Xl = (const uint32_t*)Xlo;
    const uint32_t* Wh = (const uint32_t*)Whi;
    const uint32_t* Wl = (const uint32_t*)Wlo;

    float D[2][NTN][4];
#pragma unroll
    for (int mi = 0; mi < 2; mi++)
#pragma unroll
        for (int nt = 0; nt < NTN; nt++)
#pragma unroll
            for (int c = 0; c < 4; c++) D[mi][nt][c] = 0.f;

#pragma unroll
    for (int kc = 0; kc < 7; kc++) {
        uint32_t Ah[2][4], Al[2][4];
#pragma unroll
        for (int mi = 0; mi < 2; mi++) {
            int r = ((2 * w + mi) * 16 + g) * 60 + kc * 8 + t;
            Ah[mi][0] = Xh[r];           Ah[mi][1] = Xh[r + 8 * 60];
            Ah[mi][2] = Xh[r + 4];       Ah[mi][3] = Xh[r + 8 * 60 + 4];
            Al[mi][0] = Xl[r];           Al[mi][1] = Xl[r + 8 * 60];
            Al[mi][2] = Xl[r + 4];       Al[mi][3] = Xl[r + 8 * 60 + 4];
        }
        uint32_t Bh[NTN][2], Bl[NTN][2];
#pragma unroll
        for (int nt = 0; nt < NTN; nt++) {
            int rb = (nt * 8 + g) * 60 + kc * 8 + t;
            Bh[nt][0] = Wh[rb]; Bh[nt][1] = Wh[rb + 4];
            Bl[nt][0] = Wl[rb]; Bl[nt][1] = Wl[rb + 4];
        }
#pragma unroll
        for (int mi = 0; mi < 2; mi++)
#pragma unroll
            for (int nt = 0; nt < NTN; nt++) {
                mma16816(D[mi][nt], Ah[mi], Bh[nt]);
                mma16816(D[mi][nt], Al[mi], Bh[nt]);
                mma16816(D[mi][nt], Ah[mi], Bl[nt]);
            }
    }

    // ---- epilogue: c0,c1 -> row g cols 2t,2t+1 ; c2,c3 -> row g+8 ----
#pragma unroll
    for (int mi = 0; mi < 2; mi++) {
        size_t r1 = row0 + (2 * w + mi) * 16 + g;
        size_t r2 = r1 + 8;
#pragma unroll
        for (int nt = 0; nt < NTN; nt++) {
            int col = nt * 8 + 2 * t;
            if (col + 1 < NVAL + (NVAL & 1) && col < NVAL) {
                float2 bb = *(float2*)&bs[col];
                float2 o1, o2;
                o1.x = D[mi][nt][0] + bb.x; o1.y = D[mi][nt][1] + bb.y;
                o2.x = D[mi][nt][2] + bb.x; o2.y = D[mi][nt][3] + bb.y;
                if (!DEC) {
                    *(float2*)(Y + r1 * HH + col) = o1;
                    *(float2*)(Y + r2 * HH + col) = o2;
                } else {
                    *(float2*)(Y + ((r1 & 511) * TT + (r1 >> 9)) * VV + col) = o1;
                    *(float2*)(Y + ((r2 & 511) * TT + (r2 >> 9)) * VV + col) = o2;
                }
            }
        }
    }
}

// ---------------------------------------------------------------------------
// embedding gather (2 launches; ncu -s5 -> launch idx5 = proj#2)
// ---------------------------------------------------------------------------
__global__ void k_gather(const int* __restrict__ ids,
                         const float* __restrict__ emb,
                         float* __restrict__ out, int base, int count) {
    int idx = base + blockIdx.x * blockDim.x + threadIdx.x;
    if (idx >= base + count || idx >= TT * BB * 25) return;
    int c  = idx % 25;
    int tb = idx / 25;
    int b  = tb % BB;
    int t  = tb / BB;
    int id = ids[(size_t)b * TT + t];
    float4 v = ((const float4*)(emb + (size_t)id * HH))[c];
    ((float4*)(out + ((size_t)t * BB + b) * HH))[c] = v;
}

// ---------------------------------------------------------------------------
// recurrent scan (R6 best): h_new = tanh(xin[t] + h @ Wh^T), in-place.
// 128 blocks x 256 thr = two independent 128-thr groups (2 rows each).
// ---------------------------------------------------------------------------
__global__ void __launch_bounds__(256, 1) k_rnn(float* __restrict__ XY,
                                                const float* __restrict__ W,
                                                float* __restrict__ hout) {
    __shared__ __align__(16) float hs[2][4][104];

    int tid = threadIdx.x;
    int g   = tid >> 7;
    int k   = tid & 127;
    int kk  = (k < HH) ? k : (HH - 1);
    int r0  = g * 2;

    ulonglong2 wv[25];
    const ulonglong2* Wg = (const ulonglong2*)W;
#pragma unroll
    for (int i = 0; i < 25; i++) wv[i] = Wg[kk * 25 + i];

    if (tid < 104) {
        hs[0][0][tid] = 0.f; hs[0][1][tid] = 0.f;
        hs[0][2][tid] = 0.f; hs[0][3][tid] = 0.f;
    }
    __syncthreads();

    int b0 = blockIdx.x * 4 + r0;
    const size_t st = (size_t)BB * HH;
    const float* px = XY + (size_t)b0 * HH + kk;

    float c0 = px[0], c1 = px[HH];
    int p = 0;

    for (int t = 0; t < TT; t++) {
        size_t tn = (size_t)((t + 1 < TT) ? t + 1 : t) * st;
        float n0 = px[tn], n1 = px[tn + HH];

        ull a0l = 0, a0h = 0, a1l = 0, a1h = 0;
        const ulonglong2* h0p = (const ulonglong2*)&hs[p][r0][0];
        const ulonglong2* h1p = (const ulonglong2*)&hs[p][r0 + 1][0];
#pragma unroll
        for (int j = 0; j < 25; j++) {
            ulonglong2 w  = wv[j];
            ulonglong2 h0 = h0p[j];
            ulonglong2 h1 = h1p[j];
            fma2(a0l, w.x, h0.x); fma2(a0h, w.y, h0.y);
            fma2(a1l, w.x, h1.x); fma2(a1h, w.y, h1.y);
        }
        float z0 = ftanh(red2(a0l) + red2(a0h) + c0);
        float z1 = ftanh(red2(a1l) + red2(a1h) + c1);

        if (k < HH) {
            hs[p ^ 1][r0][k]     = z0;
            hs[p ^ 1][r0 + 1][k] = z1;
            float* py = XY + (size_t)t * st + (size_t)b0 * HH + k;
            py[0] = z0; py[HH] = z1;
        }
        __syncthreads();
        p ^= 1;
        c0 = n0; c1 = n1;
    }

    if (k < HH) {
        hout[(size_t)b0 * HH + k]       = hs[p][r0][k];
        hout[(size_t)(b0 + 1) * HH + k] = hs[p][r0 + 1][k];
    }
}

// ---------------------------------------------------------------------------
extern "C" void kernel_launch(void* const* d_in, const int* in_sizes, int n_in,
                              void* d_out, int out_size) {
    const int*   ids   = (const int*)d_in[0];
    const float* emb   = (const float*)d_in[1];
    const float* W_ih  = (const float*)d_in[2];
    const float* W_hh  = (const float*)d_in[3];
    const float* b_ih  = (const float*)d_in[4];
    const float* b_hh  = (const float*)d_in[5];
    const float* W_dec = (const float*)d_in[6];
    const float* b_dec = (const float*)d_in[7];
    float* out = (float*)d_out;

    float *bufA, *bufB;
    __nv_bfloat16 *whi, *wlo;
    cudaGetSymbolAddress((void**)&bufA, g_bufA);
    cudaGetSymbolAddress((void**)&bufB, g_bufB);
    cudaGetSymbolAddress((void**)&whi, g_Whi);
    cudaGetSymbolAddress((void**)&wlo, g_Wlo);

    auto kproj = k_gemm<104, 13, 100, false>;
    auto kdec  = k_gemm<64,  8,  62,  true>;
    // smem: X 2*128*120*2 + W 2*NPAD*120*2 + bias NPAD*4
    const int proj_smem = 61440 + 2 * 104 * 120 * 2 + 104 * 4;   // 111,776 B
    const int dec_smem  = 61440 + 2 * 64 * 120 * 2 + 64 * 4;     //  92,416 B
    cudaFuncSetAttribute(kproj, cudaFuncAttributeMaxDynamicSharedMemorySize, proj_smem);
    cudaFuncSetAttribute(kdec,  cudaFuncAttributeMaxDynamicSharedMemorySize, dec_smem);

    float* hid = out + (size_t)BB * TT * VV;
    const int NT = (TT * BB) / 128;   // 4096 tiles

    // 0) weight prep (once)
    k_wprep<<<2, 256>>>(W_ih, W_dec, whi, wlo);

    // 1-2) gather in 2 launches
    {
        int total = TT * BB * 25;
        int half = total / 2;
        k_gather<<<(half + 255) / 256, 256>>>(ids, emb, bufA, 0, half);
        k_gather<<<(total - half + 255) / 256, 256>>>(ids, emb, bufA, half, total - half);
    }

    // layer 0
    kproj<<<NT, 128, proj_smem>>>(bufA, whi, wlo, b_ih, b_hh, bufB);
    k_rnn<<<BB / 4, 256>>>(bufB, W_hh, hid);
    // layer 1
    kproj<<<NT, 128, proj_smem>>>(bufB, whi + 104 * 112, wlo + 104 * 112,
                                  b_ih + 100, b_hh + 100, bufA);
    k_rnn<<<BB / 4, 256>>>(bufA, W_hh + 10000, hid + (size_t)BB * HH);
    // layer 2
    kproj<<<NT, 128, proj_smem>>>(bufA, whi + 208 * 112, wlo + 208 * 112,
                                  b_ih + 200, b_hh + 200, bufB);
    k_rnn<<<BB / 4, 256>>>(bufB, W_hh + 20000, hid + 2 * (size_t)BB * HH);

    // decoder
    kdec<<<NT, 128, dec_smem>>>(bufB, whi + 312 * 112, wlo + 312 * 112,
                                b_dec, nullptr, out);
}